// round 6
// baseline (speedup 1.0000x reference)
#include <cuda_runtime.h>

// Row-normalize: out[b,i,j] = adj[b,i,j] / sum_j adj[b,i,j]  (nan/inf inv -> 0)
// Two tensors of [16, 1024, 1024] fp32; output = concat(out0, out1).
//
// One WARP per row: 32 lanes x 8 float4 = entire 1024-elem row in registers.
// Shuffle-only reduction -> no __syncthreads, no smem, no cross-warp coupling.
// 8 independent front-batched LDG.128 per thread (MLP=8).

constexpr int N        = 1024;   // row length
constexpr int THREADS  = 256;    // 8 warps = 8 rows per CTA
constexpr int WARPS    = THREADS / 32;
constexpr int VPT      = 8;      // float4 per thread (32 lanes * 8 * 4 = 1024)

__global__ __launch_bounds__(THREADS)
void row_norm_kernel(const float* __restrict__ in0,
                     const float* __restrict__ in1,
                     float* __restrict__ out,
                     int rows_per_tensor)   // 16384
{
    const int lane = threadIdx.x & 31;
    const int wid  = threadIdx.x >> 5;

    const long long row = (long long)blockIdx.x * WARPS + wid;
    const bool second = row >= rows_per_tensor;
    const float* __restrict__ src = second ? in1 : in0;
    const long long local_row = second ? (row - rows_per_tensor) : row;

    const float4* __restrict__ src_row =
        reinterpret_cast<const float4*>(src) + local_row * (N / 4);
    float4* __restrict__ dst_row =
        reinterpret_cast<float4*>(out) + row * (N / 4);

    // Front-batch 8 independent 128B-coalesced loads (MLP=8).
    float4 v[VPT];
    #pragma unroll
    for (int i = 0; i < VPT; ++i)
        v[i] = __ldcs(src_row + lane + i * 32);

    float partial = 0.0f;
    #pragma unroll
    for (int i = 0; i < VPT; ++i)
        partial += ((v[i].x + v[i].y) + (v[i].z + v[i].w));

    // Warp-only reduction — the row lives entirely in this warp.
    #pragma unroll
    for (int off = 16; off > 0; off >>= 1)
        partial += __shfl_xor_sync(0xFFFFFFFFu, partial, off);

    float inv = 1.0f / partial;
    if (!isfinite(inv)) inv = 0.0f;

    #pragma unroll
    for (int i = 0; i < VPT; ++i) {
        v[i].x *= inv; v[i].y *= inv; v[i].z *= inv; v[i].w *= inv;
        __stcs(dst_row + lane + i * 32, v[i]);
    }
}

extern "C" void kernel_launch(void* const* d_in, const int* in_sizes, int n_in,
                              void* d_out, int out_size)
{
    const float* adj0 = (const float*)d_in[0];
    const float* adj1 = (const float*)d_in[1];
    float* out = (float*)d_out;

    const int rows_per_tensor = in_sizes[0] / N;          // 16384
    const int total_rows = 2 * rows_per_tensor;           // 32768
    const int grid = total_rows / WARPS;                  // 4096

    row_norm_kernel<<<grid, THREADS>>>(adj0, adj1, out, rows_per_tensor);
}